// round 1
// baseline (speedup 1.0000x reference)
#include <cuda_runtime.h>

#define Bb 4
#define Tt 2048
#define Ee 512
#define KBLK 64
#define NBLK 32            // Tt / KBLK
#define MROWS (Bb * Tt)    // 8192
#define COMB_W (2 * Ee)    // 1024

// Scratch (allocation-free rule: __device__ globals)
__device__ float g_K[MROWS * Ee];
__device__ float g_Q[MROWS * Ee];
__device__ float g_V[MROWS * Ee];
__device__ float g_comb[MROWS * COMB_W];

// ---------------------------------------------------------------------------
// Generic NT SGEMM: C[m,n] = sum_k A[m*K+k] * W[n*K+k] + bias[n]
// BM=BN=64, BK=16, 256 threads, 4x4 micro-tile per thread.
// Requires M%64==0, N%64==0, K%16==0.
// ---------------------------------------------------------------------------
__global__ __launch_bounds__(256) void gemm_nt(
    const float* __restrict__ A, const float* __restrict__ W,
    const float* __restrict__ bias, float* __restrict__ C,
    int M, int N, int Kd)
{
    __shared__ float As[16][68];
    __shared__ float Bs[16][68];

    const int tid = threadIdx.x;
    const int m0 = blockIdx.y * 64;
    const int n0 = blockIdx.x * 64;
    const int ty = tid >> 4;          // 0..15
    const int tx = tid & 15;          // 0..15
    const int lr = tid >> 2;          // 0..63 (tile row for loads)
    const int lk = (tid & 3) * 4;     // 0,4,8,12 (k-subchunk)

    const float* Ap = A + (size_t)(m0 + lr) * Kd + lk;
    const float* Wp = W + (size_t)(n0 + lr) * Kd + lk;

    float acc[4][4] = {};

    for (int k0 = 0; k0 < Kd; k0 += 16) {
        float4 va = *(const float4*)(Ap + k0);
        float4 vb = *(const float4*)(Wp + k0);
        As[lk + 0][lr] = va.x; As[lk + 1][lr] = va.y;
        As[lk + 2][lr] = va.z; As[lk + 3][lr] = va.w;
        Bs[lk + 0][lr] = vb.x; Bs[lk + 1][lr] = vb.y;
        Bs[lk + 2][lr] = vb.z; Bs[lk + 3][lr] = vb.w;
        __syncthreads();
#pragma unroll
        for (int kk = 0; kk < 16; kk++) {
            float4 ra = *(const float4*)&As[kk][ty * 4];
            float4 rb = *(const float4*)&Bs[kk][tx * 4];
            float a_[4] = {ra.x, ra.y, ra.z, ra.w};
            float b_[4] = {rb.x, rb.y, rb.z, rb.w};
#pragma unroll
            for (int i = 0; i < 4; i++)
#pragma unroll
                for (int j = 0; j < 4; j++)
                    acc[i][j] += a_[i] * b_[j];
        }
        __syncthreads();
    }

    float4 bb = *(const float4*)&bias[n0 + tx * 4];
    const float badd[4] = {bb.x, bb.y, bb.z, bb.w};
#pragma unroll
    for (int i = 0; i < 4; i++) {
        size_t m = (size_t)(m0 + ty * 4 + i);
        float4 v;
        v.x = acc[i][0] + badd[0];
        v.y = acc[i][1] + badd[1];
        v.z = acc[i][2] + badd[2];
        v.w = acc[i][3] + badd[3];
        *(float4*)(C + m * N + n0 + tx * 4) = v;
    }
}

// ---------------------------------------------------------------------------
// head1: per (batch, 64-block): S[r][c] = K[r]·Q[c] (c<=r within block),
//        out1[r][e] = sum_c S[r][c] * V[c][e]   -> comb[..., 0:512]
// ---------------------------------------------------------------------------
__global__ __launch_bounds__(256) void head1_kernel()
{
    const int blk = blockIdx.x;
    const int b   = blockIdx.y;
    const int tid = threadIdx.x;
    const int ty = tid >> 4, tx = tid & 15;
    const int lr = tid >> 2, lk = (tid & 3) * 4;

    const size_t base = ((size_t)b * Tt + (size_t)blk * KBLK) * Ee;

    __shared__ float Ks[16][68];
    __shared__ float Qs[16][68];
    __shared__ float Ssh[64][68];   // transposed: Ssh[c][r]
    __shared__ float Vs[64][68];

    // Phase 1: S = K_blk @ Q_blk^T over E=512
    float acc[4][4] = {};
    for (int e0 = 0; e0 < Ee; e0 += 16) {
        float4 vk = *(const float4*)(g_K + base + (size_t)lr * Ee + e0 + lk);
        float4 vq = *(const float4*)(g_Q + base + (size_t)lr * Ee + e0 + lk);
        Ks[lk + 0][lr] = vk.x; Ks[lk + 1][lr] = vk.y;
        Ks[lk + 2][lr] = vk.z; Ks[lk + 3][lr] = vk.w;
        Qs[lk + 0][lr] = vq.x; Qs[lk + 1][lr] = vq.y;
        Qs[lk + 2][lr] = vq.z; Qs[lk + 3][lr] = vq.w;
        __syncthreads();
#pragma unroll
        for (int kk = 0; kk < 16; kk++) {
            float4 ra = *(const float4*)&Ks[kk][ty * 4];
            float4 rb = *(const float4*)&Qs[kk][tx * 4];
            float a_[4] = {ra.x, ra.y, ra.z, ra.w};
            float b_[4] = {rb.x, rb.y, rb.z, rb.w};
#pragma unroll
            for (int i = 0; i < 4; i++)
#pragma unroll
                for (int j = 0; j < 4; j++)
                    acc[i][j] += a_[i] * b_[j];
        }
        __syncthreads();
    }

    // Mask (keep c <= r) and store transposed
#pragma unroll
    for (int i = 0; i < 4; i++)
#pragma unroll
        for (int j = 0; j < 4; j++) {
            int r = ty * 4 + i, c = tx * 4 + j;
            Ssh[c][r] = (c <= r) ? acc[i][j] : 0.0f;
        }
    __syncthreads();

    // Phase 2: out = S @ V_blk, tiling e in chunks of 64
    for (int e0 = 0; e0 < Ee; e0 += 64) {
#pragma unroll
        for (int l = 0; l < 4; l++) {
            int c = ty + l * 16;
            int ec = tx * 4;
            *(float4*)&Vs[c][ec] =
                *(const float4*)(g_V + base + (size_t)c * Ee + e0 + ec);
        }
        __syncthreads();
        float o[4][4] = {};
#pragma unroll 8
        for (int c = 0; c < 64; c++) {
            float4 rs = *(const float4*)&Ssh[c][ty * 4];
            float4 rv = *(const float4*)&Vs[c][tx * 4];
            float s_[4] = {rs.x, rs.y, rs.z, rs.w};
            float v_[4] = {rv.x, rv.y, rv.z, rv.w};
#pragma unroll
            for (int i = 0; i < 4; i++)
#pragma unroll
                for (int j = 0; j < 4; j++)
                    o[i][j] += s_[i] * v_[j];
        }
#pragma unroll
        for (int i = 0; i < 4; i++) {
            size_t row = (size_t)b * Tt + (size_t)blk * KBLK + ty * 4 + i;
            float4 v; v.x = o[i][0]; v.y = o[i][1]; v.z = o[i][2]; v.w = o[i][3];
            *(float4*)(g_comb + row * COMB_W + e0 + tx * 4) = v;
        }
        __syncthreads();
    }
}

// ---------------------------------------------------------------------------
// head2: rows attend to the 32 block-start columns (col = i*64), causal:
//        for row-tile rt, mask is uniformly i <= rt.
//        out2[r][e] = sum_{i<=rt} (K[r]·Q[i*64]) * V[i*64][e] -> comb[...,512:]
// ---------------------------------------------------------------------------
__global__ __launch_bounds__(256) void head2_kernel()
{
    const int rt = blockIdx.x;   // row tile (0..31)
    const int b  = blockIdx.y;
    const int tid = threadIdx.x;
    const int ty = tid >> 4, tx = tid & 15;
    const int lr = tid >> 2, lk = (tid & 3) * 4;

    const size_t kbase = ((size_t)b * Tt + (size_t)rt * KBLK) * Ee;

    __shared__ float Ks[16][68];
    __shared__ float Qs[16][36];   // [kk][i], 32 start-cols
    __shared__ float S2[32][68];   // transposed: S2[i][r]
    __shared__ float Vs[32][68];

    // Phase 1: S2[r][i] = K[rt*64+r] · Q[i*64]
    float acc[4][2] = {};
    for (int e0 = 0; e0 < Ee; e0 += 16) {
        float4 vk = *(const float4*)(g_K + kbase + (size_t)lr * Ee + e0 + lk);
        Ks[lk + 0][lr] = vk.x; Ks[lk + 1][lr] = vk.y;
        Ks[lk + 2][lr] = vk.z; Ks[lk + 3][lr] = vk.w;
        if (tid < 128) {
            int qi = tid >> 2;   // 0..31
            float4 vq = *(const float4*)(g_Q +
                ((size_t)b * Tt + (size_t)qi * KBLK) * Ee + e0 + lk);
            Qs[lk + 0][qi] = vq.x; Qs[lk + 1][qi] = vq.y;
            Qs[lk + 2][qi] = vq.z; Qs[lk + 3][qi] = vq.w;
        }
        __syncthreads();
#pragma unroll
        for (int kk = 0; kk < 16; kk++) {
            float4 ra = *(const float4*)&Ks[kk][ty * 4];
            float a_[4] = {ra.x, ra.y, ra.z, ra.w};
            float q0 = Qs[kk][tx * 2 + 0];
            float q1 = Qs[kk][tx * 2 + 1];
#pragma unroll
            for (int i = 0; i < 4; i++) {
                acc[i][0] += a_[i] * q0;
                acc[i][1] += a_[i] * q1;
            }
        }
        __syncthreads();
    }

    // Mask (keep i <= rt) and store transposed
#pragma unroll
    for (int i = 0; i < 4; i++)
#pragma unroll
        for (int j = 0; j < 2; j++) {
            int r = ty * 4 + i, ii = tx * 2 + j;
            S2[ii][r] = (ii <= rt) ? acc[i][j] : 0.0f;
        }
    __syncthreads();

    // Phase 2: out2 = S2 @ V_starts, e tiled by 64
    for (int e0 = 0; e0 < Ee; e0 += 64) {
#pragma unroll
        for (int l = 0; l < 2; l++) {
            int ii = (tid >> 4) + l * 16;   // 0..31
            int ec = (tid & 15) * 4;
            *(float4*)&Vs[ii][ec] = *(const float4*)(g_V +
                ((size_t)b * Tt + (size_t)ii * KBLK) * Ee + e0 + ec);
        }
        __syncthreads();
        float o[4][4] = {};
#pragma unroll 8
        for (int ii = 0; ii < 32; ii++) {
            float4 rs = *(const float4*)&S2[ii][ty * 4];
            float4 rv = *(const float4*)&Vs[ii][tx * 4];
            float s_[4] = {rs.x, rs.y, rs.z, rs.w};
            float v_[4] = {rv.x, rv.y, rv.z, rv.w};
#pragma unroll
            for (int i = 0; i < 4; i++)
#pragma unroll
                for (int j = 0; j < 4; j++)
                    o[i][j] += s_[i] * v_[j];
        }
#pragma unroll
        for (int i = 0; i < 4; i++) {
            size_t row = (size_t)b * Tt + (size_t)rt * KBLK + ty * 4 + i;
            float4 v; v.x = o[i][0]; v.y = o[i][1]; v.z = o[i][2]; v.w = o[i][3];
            *(float4*)(g_comb + row * COMB_W + Ee + e0 + tx * 4) = v;
        }
        __syncthreads();
    }
}

// ---------------------------------------------------------------------------
extern "C" void kernel_launch(void* const* d_in, const int* in_sizes, int n_in,
                              void* d_out, int out_size)
{
    const float* x  = (const float*)d_in[0];
    const float* Wk = (const float*)d_in[1];
    const float* bk = (const float*)d_in[2];
    const float* Wq = (const float*)d_in[3];
    const float* bq = (const float*)d_in[4];
    const float* Wv = (const float*)d_in[5];
    const float* bv = (const float*)d_in[6];
    const float* Wu = (const float*)d_in[7];
    const float* bu = (const float*)d_in[8];
    float* out = (float*)d_out;

    float *pK, *pQ, *pV, *pC;
    cudaGetSymbolAddress((void**)&pK, g_K);
    cudaGetSymbolAddress((void**)&pQ, g_Q);
    cudaGetSymbolAddress((void**)&pV, g_V);
    cudaGetSymbolAddress((void**)&pC, g_comb);

    // QKV projections
    dim3 gridP(Ee / 64, MROWS / 64);
    gemm_nt<<<gridP, 256>>>(x, Wk, bk, pK, MROWS, Ee, Ee);
    gemm_nt<<<gridP, 256>>>(x, Wq, bq, pQ, MROWS, Ee, Ee);
    gemm_nt<<<gridP, 256>>>(x, Wv, bv, pV, MROWS, Ee, Ee);

    // Sparse heads -> comb
    head1_kernel<<<dim3(NBLK, Bb), 256>>>();
    head2_kernel<<<dim3(NBLK, Bb), 256>>>();

    // Final projection: out = comb @ Wu^T + bu
    gemm_nt<<<dim3(Ee / 64, MROWS / 64), 256>>>(pC, Wu, bu, out,
                                                MROWS, Ee, COMB_W);
}

// round 3
// speedup vs baseline: 2.0325x; 2.0325x over previous
#include <cuda_runtime.h>
#include <cuda_bf16.h>
#include <cstdint>

#define Bb 4
#define Tt 2048
#define Ee 512
#define KBLK 64
#define NBLK 32
#define MROWS (Bb * Tt)        // 8192
#define COMB_W (2 * Ee)        // 1024
#define NQKV (3 * Ee)          // 1536

// ---------------- scratch (__device__ globals; allocation-free rule) -------
__device__ float g_KQV[MROWS * NQKV];
__device__ float g_comb[MROWS * COMB_W];
__device__ __nv_bfloat16 g_xhi[MROWS * Ee];
__device__ __nv_bfloat16 g_xlo[MROWS * Ee];
__device__ __nv_bfloat16 g_Whi[NQKV * Ee];
__device__ __nv_bfloat16 g_Wlo[NQKV * Ee];
__device__ __nv_bfloat16 g_Uhi[Ee * COMB_W];
__device__ __nv_bfloat16 g_Ulo[Ee * COMB_W];
__device__ __nv_bfloat16 g_chi[MROWS * COMB_W];
__device__ __nv_bfloat16 g_clo[MROWS * COMB_W];
__device__ float g_bias[NQKV];

// ---------------- PTX helpers ----------------------------------------------
__device__ __forceinline__ uint32_t smem_u32(const void* p) {
    uint32_t a;
    asm("{ .reg .u64 t; cvta.to.shared.u64 t, %1; cvt.u32.u64 %0, t; }"
        : "=r"(a) : "l"(p));
    return a;
}
#define CP_ASYNC16(dst, src) \
    asm volatile("cp.async.cg.shared.global [%0], [%1], 16;" :: "r"(dst), "l"(src))
#define CP_COMMIT() asm volatile("cp.async.commit_group;" ::: "memory")
#define CP_WAIT1()  asm volatile("cp.async.wait_group 1;" ::: "memory")
#define CP_WAIT0()  asm volatile("cp.async.wait_group 0;" ::: "memory")

__device__ __forceinline__ void ldm_x4(uint32_t* r, uint32_t addr) {
    asm volatile("ldmatrix.sync.aligned.m8n8.x4.shared.b16 {%0,%1,%2,%3}, [%4];"
                 : "=r"(r[0]), "=r"(r[1]), "=r"(r[2]), "=r"(r[3]) : "r"(addr));
}
__device__ __forceinline__ void mma16816(float* c, const uint32_t* a, const uint32_t* b) {
    asm volatile("mma.sync.aligned.m16n8k16.row.col.f32.bf16.bf16.f32 "
                 "{%0,%1,%2,%3}, {%4,%5,%6,%7}, {%8,%9}, {%0,%1,%2,%3};"
                 : "+f"(c[0]), "+f"(c[1]), "+f"(c[2]), "+f"(c[3])
                 : "r"(a[0]), "r"(a[1]), "r"(a[2]), "r"(a[3]), "r"(b[0]), "r"(b[1]));
}

// ---------------- split-bf16 tensor-core NT GEMM ---------------------------
// C[m,n] = sum_k A[m,k]*B[n,k] + bias[n] via Ah*Bh + Ah*Bl + Al*Bh
// 128x128 tile, BK=32, double-buffered cp.async, 8 warps (warp tile 32x64).
// smem per stage: 4 tiles x (128 rows x 80B) = 40960 B; x2 stages = 81920 B.
#define ROWB 80
#define TILEB (128 * ROWB)          // 10240
#define STAGEB (4 * TILEB)          // 40960
#define GM_SMEM (2 * STAGEB)        // 81920

__global__ __launch_bounds__(256) void gemm_mma(
    const __nv_bfloat16* __restrict__ Ahi, const __nv_bfloat16* __restrict__ Alo,
    const __nv_bfloat16* __restrict__ Bhi, const __nv_bfloat16* __restrict__ Blo,
    const float* __restrict__ bias, float* __restrict__ C, int Kd, int Nout)
{
    extern __shared__ char smem[];
    const uint32_t sbase = smem_u32(smem);
    const int tid = threadIdx.x;
    const int wid = tid >> 5, lane = tid & 31;
    const int warp_m = wid & 3, warp_n = wid >> 2;      // 4 x 2 warps
    const int m0 = blockIdx.y * 128, n0 = blockIdx.x * 128;

    // global load mapping: 2 chunks of 16B per tile per thread
    const int r0 = tid >> 2;            // 0..63
    const int r1 = r0 + 64;
    const int c0 = (tid & 3) * 16;      // byte offset in 64B row
    const int ce = (tid & 3) * 8;       // element offset

    auto load_stage = [&](int s, int k0) {
        uint32_t dst = sbase + (s & 1) * STAGEB;
        const __nv_bfloat16* srcs[4] = {
            Ahi + (size_t)(m0 + r0) * Kd + k0 + ce,
            Alo + (size_t)(m0 + r0) * Kd + k0 + ce,
            Bhi + (size_t)(n0 + r0) * Kd + k0 + ce,
            Blo + (size_t)(n0 + r0) * Kd + k0 + ce };
#pragma unroll
        for (int t = 0; t < 4; t++) {
            uint32_t d = dst + t * TILEB;
            CP_ASYNC16(d + r0 * ROWB + c0, srcs[t]);
            CP_ASYNC16(d + r1 * ROWB + c0, srcs[t] + (size_t)64 * Kd);
        }
        CP_COMMIT();
    };

    float acc[2][8][4] = {};

    const int nstages = Kd >> 5;
    load_stage(0, 0);

    for (int s = 0; s < nstages; s++) {
        if (s + 1 < nstages) { load_stage(s + 1, (s + 1) << 5); CP_WAIT1(); }
        else                 { CP_WAIT0(); }
        __syncthreads();

        const uint32_t st = sbase + (s & 1) * STAGEB;
        const uint32_t sAh = st, sAl = st + TILEB, sBh = st + 2 * TILEB, sBl = st + 3 * TILEB;

        // A address: row = warp_m*32 + mt*16 + lane%16 ; koff = ks*32 + (lane/16)*16
        const uint32_t aRow = (uint32_t)(warp_m * 32 + (lane & 15)) * ROWB + ((lane >> 4) & 1) * 16;
        // B address for pair p (x4 covers ntiles 2p,2p+1):
        const int g = lane >> 3, lr = lane & 7;
        const uint32_t bRowBase = (uint32_t)(warp_n * 64 + ((g >> 1) & 1) * 8 + lr) * ROWB + (g & 1) * 16;

#pragma unroll
        for (int ks = 0; ks < 2; ks++) {
            uint32_t ah[2][4], al[2][4];
#pragma unroll
            for (int mt = 0; mt < 2; mt++) {
                uint32_t ao = aRow + (uint32_t)mt * 16 * ROWB + ks * 32;
                ldm_x4(ah[mt], sAh + ao);
                ldm_x4(al[mt], sAl + ao);
            }
#pragma unroll
            for (int p = 0; p < 4; p++) {
                uint32_t bo = bRowBase + (uint32_t)p * 16 * ROWB + ks * 32;
                uint32_t bh[4], bl[4];
                ldm_x4(bh, sBh + bo);
                ldm_x4(bl, sBl + bo);
#pragma unroll
                for (int mt = 0; mt < 2; mt++)
#pragma unroll
                    for (int j = 0; j < 2; j++) {
                        float* cc = acc[mt][2 * p + j];
                        mma16816(cc, ah[mt], &bh[j * 2]);
                        mma16816(cc, ah[mt], &bl[j * 2]);
                        mma16816(cc, al[mt], &bh[j * 2]);
                    }
            }
        }
        __syncthreads();
    }

    // epilogue
    const int mrow = m0 + warp_m * 32 + (lane >> 2);
    const int ncol0 = n0 + warp_n * 64 + (lane & 3) * 2;
#pragma unroll
    for (int mt = 0; mt < 2; mt++)
#pragma unroll
        for (int nt = 0; nt < 8; nt++) {
            int m = mrow + mt * 16;
            int n = ncol0 + nt * 8;
            float2 bv = *(const float2*)(bias + n);
            const float* cc = acc[mt][nt];
            float2 v0; v0.x = cc[0] + bv.x; v0.y = cc[1] + bv.y;
            float2 v1; v1.x = cc[2] + bv.x; v1.y = cc[3] + bv.y;
            *(float2*)(C + (size_t)m * Nout + n) = v0;
            *(float2*)(C + (size_t)(m + 8) * Nout + n) = v1;
        }
}

// ---------------- conversion kernels ---------------------------------------
__global__ void split_kernel(const float* __restrict__ in,
                             __nv_bfloat16* __restrict__ hi,
                             __nv_bfloat16* __restrict__ lo, int n)
{
    for (int i = blockIdx.x * blockDim.x + threadIdx.x; i < n; i += gridDim.x * blockDim.x) {
        float v = in[i];
        __nv_bfloat16 h = __float2bfloat16(v);
        hi[i] = h;
        lo[i] = __float2bfloat16(v - __bfloat162float(h));
    }
}
__global__ void stack_bias_kernel(const float* bk, const float* bq, const float* bv)
{
    int i = blockIdx.x * blockDim.x + threadIdx.x;
    if (i < Ee) {
        g_bias[i] = bk[i];
        g_bias[Ee + i] = bq[i];
        g_bias[2 * Ee + i] = bv[i];
    }
}

// ---------------- sparse heads (SIMT fp32, stacked-KQV layout) --------------
__global__ __launch_bounds__(256) void head1_kernel()
{
    const int blk = blockIdx.x, b = blockIdx.y;
    const int tid = threadIdx.x;
    const int ty = tid >> 4, tx = tid & 15;
    const int lr = tid >> 2, lk = (tid & 3) * 4;
    const size_t rbase = (size_t)b * Tt + (size_t)blk * KBLK;

    __shared__ float Ks[16][68];
    __shared__ float Qs[16][68];
    __shared__ float Ssh[64][68];
    __shared__ float Vs[64][68];

    float acc[4][4] = {};
    for (int e0 = 0; e0 < Ee; e0 += 16) {
        const float* rp = g_KQV + (rbase + lr) * NQKV;
        float4 vk = *(const float4*)(rp + e0 + lk);
        float4 vq = *(const float4*)(rp + Ee + e0 + lk);
        Ks[lk + 0][lr] = vk.x; Ks[lk + 1][lr] = vk.y;
        Ks[lk + 2][lr] = vk.z; Ks[lk + 3][lr] = vk.w;
        Qs[lk + 0][lr] = vq.x; Qs[lk + 1][lr] = vq.y;
        Qs[lk + 2][lr] = vq.z; Qs[lk + 3][lr] = vq.w;
        __syncthreads();
#pragma unroll
        for (int kk = 0; kk < 16; kk++) {
            float4 ra = *(const float4*)&Ks[kk][ty * 4];
            float4 rb = *(const float4*)&Qs[kk][tx * 4];
            float a_[4] = {ra.x, ra.y, ra.z, ra.w};
            float b_[4] = {rb.x, rb.y, rb.z, rb.w};
#pragma unroll
            for (int i = 0; i < 4; i++)
#pragma unroll
                for (int j = 0; j < 4; j++)
                    acc[i][j] += a_[i] * b_[j];
        }
        __syncthreads();
    }
#pragma unroll
    for (int i = 0; i < 4; i++)
#pragma unroll
        for (int j = 0; j < 4; j++) {
            int r = ty * 4 + i, c = tx * 4 + j;
            Ssh[c][r] = (c <= r) ? acc[i][j] : 0.0f;
        }
    __syncthreads();

    for (int e0 = 0; e0 < Ee; e0 += 64) {
#pragma unroll
        for (int l = 0; l < 4; l++) {
            int c = ty + l * 16;
            *(float4*)&Vs[c][tx * 4] =
                *(const float4*)(g_KQV + (rbase + c) * NQKV + 2 * Ee + e0 + tx * 4);
        }
        __syncthreads();
        float o[4][4] = {};
#pragma unroll 8
        for (int c = 0; c < 64; c++) {
            float4 rs = *(const float4*)&Ssh[c][ty * 4];
            float4 rv = *(const float4*)&Vs[c][tx * 4];
            float s_[4] = {rs.x, rs.y, rs.z, rs.w};
            float v_[4] = {rv.x, rv.y, rv.z, rv.w};
#pragma unroll
            for (int i = 0; i < 4; i++)
#pragma unroll
                for (int j = 0; j < 4; j++)
                    o[i][j] += s_[i] * v_[j];
        }
#pragma unroll
        for (int i = 0; i < 4; i++) {
            size_t row = rbase + ty * 4 + i;
            float4 v; v.x = o[i][0]; v.y = o[i][1]; v.z = o[i][2]; v.w = o[i][3];
            *(float4*)(g_comb + row * COMB_W + e0 + tx * 4) = v;
        }
        __syncthreads();
    }
}

__global__ __launch_bounds__(256) void head2_kernel()
{
    const int rt = blockIdx.x, b = blockIdx.y;
    const int tid = threadIdx.x;
    const int ty = tid >> 4, tx = tid & 15;
    const int lr = tid >> 2, lk = (tid & 3) * 4;
    const size_t rbase = (size_t)b * Tt + (size_t)rt * KBLK;

    __shared__ float Ks[16][68];
    __shared__ float Qs[16][36];
    __shared__ float S2[32][68];
    __shared__ float Vs[32][68];

    float acc[4][2] = {};
    for (int e0 = 0; e0 < Ee; e0 += 16) {
        float4 vk = *(const float4*)(g_KQV + (rbase + lr) * NQKV + e0 + lk);
        Ks[lk + 0][lr] = vk.x; Ks[lk + 1][lr] = vk.y;
        Ks[lk + 2][lr] = vk.z; Ks[lk + 3][lr] = vk.w;
        if (tid < 128) {
            int qi = tid >> 2;
            float4 vq = *(const float4*)(g_KQV +
                ((size_t)b * Tt + (size_t)qi * KBLK) * NQKV + Ee + e0 + lk);
            Qs[lk + 0][qi] = vq.x; Qs[lk + 1][qi] = vq.y;
            Qs[lk + 2][qi] = vq.z; Qs[lk + 3][qi] = vq.w;
        }
        __syncthreads();
#pragma unroll
        for (int kk = 0; kk < 16; kk++) {
            float4 ra = *(const float4*)&Ks[kk][ty * 4];
            float a_[4] = {ra.x, ra.y, ra.z, ra.w};
            float q0 = Qs[kk][tx * 2 + 0];
            float q1 = Qs[kk][tx * 2 + 1];
#pragma unroll
            for (int i = 0; i < 4; i++) {
                acc[i][0] += a_[i] * q0;
                acc[i][1] += a_[i] * q1;
            }
        }
        __syncthreads();
    }
#pragma unroll
    for (int i = 0; i < 4; i++)
#pragma unroll
        for (int j = 0; j < 2; j++) {
            int r = ty * 4 + i, ii = tx * 2 + j;
            S2[ii][r] = (ii <= rt) ? acc[i][j] : 0.0f;
        }
    __syncthreads();

    for (int e0 = 0; e0 < Ee; e0 += 64) {
#pragma unroll
        for (int l = 0; l < 2; l++) {
            int ii = (tid >> 4) + l * 16;
            *(float4*)&Vs[ii][(tid & 15) * 4] = *(const float4*)(g_KQV +
                ((size_t)b * Tt + (size_t)ii * KBLK) * NQKV + 2 * Ee + e0 + (tid & 15) * 4);
        }
        __syncthreads();
        float o[4][4] = {};
#pragma unroll 8
        for (int ii = 0; ii < 32; ii++) {
            float4 rs = *(const float4*)&S2[ii][ty * 4];
            float4 rv = *(const float4*)&Vs[ii][tx * 4];
            float s_[4] = {rs.x, rs.y, rs.z, rs.w};
            float v_[4] = {rv.x, rv.y, rv.z, rv.w};
#pragma unroll
            for (int i = 0; i < 4; i++)
#pragma unroll
                for (int j = 0; j < 4; j++)
                    o[i][j] += s_[i] * v_[j];
        }
#pragma unroll
        for (int i = 0; i < 4; i++) {
            size_t row = rbase + ty * 4 + i;
            float4 v; v.x = o[i][0]; v.y = o[i][1]; v.z = o[i][2]; v.w = o[i][3];
            *(float4*)(g_comb + row * COMB_W + Ee + e0 + tx * 4) = v;
        }
        __syncthreads();
    }
}

// ---------------------------------------------------------------------------
extern "C" void kernel_launch(void* const* d_in, const int* in_sizes, int n_in,
                              void* d_out, int out_size)
{
    const float* x  = (const float*)d_in[0];
    const float* Wk = (const float*)d_in[1];
    const float* bk = (const float*)d_in[2];
    const float* Wq = (const float*)d_in[3];
    const float* bq = (const float*)d_in[4];
    const float* Wv = (const float*)d_in[5];
    const float* bv = (const float*)d_in[6];
    const float* Wu = (const float*)d_in[7];
    const float* bu = (const float*)d_in[8];
    float* out = (float*)d_out;

    float *pKQV, *pComb, *pBias;
    __nv_bfloat16 *pxh, *pxl, *pWh, *pWl, *pUh, *pUl, *pch, *pcl;
    cudaGetSymbolAddress((void**)&pKQV, g_KQV);
    cudaGetSymbolAddress((void**)&pComb, g_comb);
    cudaGetSymbolAddress((void**)&pBias, g_bias);
    cudaGetSymbolAddress((void**)&pxh, g_xhi);
    cudaGetSymbolAddress((void**)&pxl, g_xlo);
    cudaGetSymbolAddress((void**)&pWh, g_Whi);
    cudaGetSymbolAddress((void**)&pWl, g_Wlo);
    cudaGetSymbolAddress((void**)&pUh, g_Uhi);
    cudaGetSymbolAddress((void**)&pUl, g_Ulo);
    cudaGetSymbolAddress((void**)&pch, g_chi);
    cudaGetSymbolAddress((void**)&pcl, g_clo);

    cudaFuncSetAttribute(gemm_mma, cudaFuncAttributeMaxDynamicSharedMemorySize, GM_SMEM);

    // splits
    split_kernel<<<1024, 256>>>(x, pxh, pxl, MROWS * Ee);
    split_kernel<<<128, 256>>>(Wk, pWh, pWl, Ee * Ee);
    split_kernel<<<128, 256>>>(Wq, pWh + Ee * Ee, pWl + Ee * Ee, Ee * Ee);
    split_kernel<<<128, 256>>>(Wv, pWh + 2 * Ee * Ee, pWl + 2 * Ee * Ee, Ee * Ee);
    split_kernel<<<256, 256>>>(Wu, pUh, pUl, Ee * COMB_W);
    stack_bias_kernel<<<2, 256>>>(bk, bq, bv);

    // fused QKV projection: [8192,1536] = x @ [Wk;Wq;Wv]^T + bias
    gemm_mma<<<dim3(NQKV / 128, MROWS / 128), 256, GM_SMEM>>>(
        pxh, pxl, pWh, pWl, pBias, pKQV, Ee, NQKV);

    // sparse heads -> comb (fp32)
    head1_kernel<<<dim3(NBLK, Bb), 256>>>();
    head2_kernel<<<dim3(NBLK, Bb), 256>>>();

    // comb -> bf16 hi/lo
    split_kernel<<<2048, 256>>>(pComb, pch, pcl, MROWS * COMB_W);

    // final projection: out = comb @ Wu^T + bu
    gemm_mma<<<dim3(Ee / 128, MROWS / 128), 256, GM_SMEM>>>(
        pch, pcl, pUh, pUl, bu, out, COMB_W, Ee);
}

// round 4
// speedup vs baseline: 2.2484x; 1.1062x over previous
#include <cuda_runtime.h>
#include <cuda_bf16.h>
#include <cstdint>

#define Bb 4
#define Tt 2048
#define Ee 512
#define KBLK 64
#define NBLK 32
#define MROWS (Bb * Tt)        // 8192
#define COMB_W (2 * Ee)        // 1024
#define NQKV (3 * Ee)          // 1536
#define KSPL 4                 // k-split factor for head score kernels
#define ESPL 4                 // e-split factor for head out kernels

// ---------------- scratch (__device__ globals) ------------------------------
__device__ float g_KQV[MROWS * NQKV];
__device__ __nv_bfloat16 g_xhi[MROWS * Ee];
__device__ __nv_bfloat16 g_xlo[MROWS * Ee];
__device__ __nv_bfloat16 g_Whi[NQKV * Ee];
__device__ __nv_bfloat16 g_Wlo[NQKV * Ee];
__device__ __nv_bfloat16 g_Uhi[Ee * COMB_W];
__device__ __nv_bfloat16 g_Ulo[Ee * COMB_W];
__device__ __nv_bfloat16 g_chi[MROWS * COMB_W];
__device__ __nv_bfloat16 g_clo[MROWS * COMB_W];
__device__ float g_bias[NQKV];
__device__ float g_S1part[KSPL * Bb * NBLK * 64 * 64];   // 8 MB
__device__ float g_S2part[KSPL * Bb * NBLK * 64 * 32];   // 4 MB

// ---------------- PTX helpers ----------------------------------------------
__device__ __forceinline__ uint32_t smem_u32(const void* p) {
    uint32_t a;
    asm("{ .reg .u64 t; cvta.to.shared.u64 t, %1; cvt.u32.u64 %0, t; }"
        : "=r"(a) : "l"(p));
    return a;
}
#define CP_ASYNC16(dst, src) \
    asm volatile("cp.async.cg.shared.global [%0], [%1], 16;" :: "r"(dst), "l"(src))
#define CP_COMMIT() asm volatile("cp.async.commit_group;" ::: "memory")
#define CP_WAIT1()  asm volatile("cp.async.wait_group 1;" ::: "memory")
#define CP_WAIT0()  asm volatile("cp.async.wait_group 0;" ::: "memory")

__device__ __forceinline__ void ldm_x4(uint32_t* r, uint32_t addr) {
    asm volatile("ldmatrix.sync.aligned.m8n8.x4.shared.b16 {%0,%1,%2,%3}, [%4];"
                 : "=r"(r[0]), "=r"(r[1]), "=r"(r[2]), "=r"(r[3]) : "r"(addr));
}
__device__ __forceinline__ void mma16816(float* c, const uint32_t* a, const uint32_t* b) {
    asm volatile("mma.sync.aligned.m16n8k16.row.col.f32.bf16.bf16.f32 "
                 "{%0,%1,%2,%3}, {%4,%5,%6,%7}, {%8,%9}, {%0,%1,%2,%3};"
                 : "+f"(c[0]), "+f"(c[1]), "+f"(c[2]), "+f"(c[3])
                 : "r"(a[0]), "r"(a[1]), "r"(a[2]), "r"(a[3]), "r"(b[0]), "r"(b[1]));
}

// ---------------- split-bf16 tensor-core NT GEMM ---------------------------
#define ROWB 80
#define TILEB (128 * ROWB)
#define STAGEB (4 * TILEB)
#define GM_SMEM (2 * STAGEB)

__global__ __launch_bounds__(256) void gemm_mma(
    const __nv_bfloat16* __restrict__ Ahi, const __nv_bfloat16* __restrict__ Alo,
    const __nv_bfloat16* __restrict__ Bhi, const __nv_bfloat16* __restrict__ Blo,
    const float* __restrict__ bias, float* __restrict__ C, int Kd, int Nout)
{
    extern __shared__ char smem[];
    const uint32_t sbase = smem_u32(smem);
    const int tid = threadIdx.x;
    const int wid = tid >> 5, lane = tid & 31;
    const int warp_m = wid & 3, warp_n = wid >> 2;
    const int m0 = blockIdx.y * 128, n0 = blockIdx.x * 128;

    const int r0 = tid >> 2;
    const int r1 = r0 + 64;
    const int c0 = (tid & 3) * 16;
    const int ce = (tid & 3) * 8;

    auto load_stage = [&](int s, int k0) {
        uint32_t dst = sbase + (s & 1) * STAGEB;
        const __nv_bfloat16* srcs[4] = {
            Ahi + (size_t)(m0 + r0) * Kd + k0 + ce,
            Alo + (size_t)(m0 + r0) * Kd + k0 + ce,
            Bhi + (size_t)(n0 + r0) * Kd + k0 + ce,
            Blo + (size_t)(n0 + r0) * Kd + k0 + ce };
#pragma unroll
        for (int t = 0; t < 4; t++) {
            uint32_t d = dst + t * TILEB;
            CP_ASYNC16(d + r0 * ROWB + c0, srcs[t]);
            CP_ASYNC16(d + r1 * ROWB + c0, srcs[t] + (size_t)64 * Kd);
        }
        CP_COMMIT();
    };

    float acc[2][8][4] = {};
    const int nstages = Kd >> 5;
    load_stage(0, 0);

    for (int s = 0; s < nstages; s++) {
        if (s + 1 < nstages) { load_stage(s + 1, (s + 1) << 5); CP_WAIT1(); }
        else                 { CP_WAIT0(); }
        __syncthreads();

        const uint32_t st = sbase + (s & 1) * STAGEB;
        const uint32_t sAh = st, sAl = st + TILEB, sBh = st + 2 * TILEB, sBl = st + 3 * TILEB;

        const uint32_t aRow = (uint32_t)(warp_m * 32 + (lane & 15)) * ROWB + ((lane >> 4) & 1) * 16;
        const int g = lane >> 3, lr = lane & 7;
        const uint32_t bRowBase = (uint32_t)(warp_n * 64 + ((g >> 1) & 1) * 8 + lr) * ROWB + (g & 1) * 16;

#pragma unroll
        for (int ks = 0; ks < 2; ks++) {
            uint32_t ah[2][4], al[2][4];
#pragma unroll
            for (int mt = 0; mt < 2; mt++) {
                uint32_t ao = aRow + (uint32_t)mt * 16 * ROWB + ks * 32;
                ldm_x4(ah[mt], sAh + ao);
                ldm_x4(al[mt], sAl + ao);
            }
#pragma unroll
            for (int p = 0; p < 4; p++) {
                uint32_t bo = bRowBase + (uint32_t)p * 16 * ROWB + ks * 32;
                uint32_t bh[4], bl[4];
                ldm_x4(bh, sBh + bo);
                ldm_x4(bl, sBl + bo);
#pragma unroll
                for (int mt = 0; mt < 2; mt++)
#pragma unroll
                    for (int j = 0; j < 2; j++) {
                        float* cc = acc[mt][2 * p + j];
                        mma16816(cc, ah[mt], &bh[j * 2]);
                        mma16816(cc, ah[mt], &bl[j * 2]);
                        mma16816(cc, al[mt], &bh[j * 2]);
                    }
            }
        }
        __syncthreads();
    }

    const int mrow = m0 + warp_m * 32 + (lane >> 2);
    const int ncol0 = n0 + warp_n * 64 + (lane & 3) * 2;
#pragma unroll
    for (int mt = 0; mt < 2; mt++)
#pragma unroll
        for (int nt = 0; nt < 8; nt++) {
            int m = mrow + mt * 16;
            int n = ncol0 + nt * 8;
            float2 bv = *(const float2*)(bias + n);
            const float* cc = acc[mt][nt];
            float2 v0; v0.x = cc[0] + bv.x; v0.y = cc[1] + bv.y;
            float2 v1; v1.x = cc[2] + bv.x; v1.y = cc[3] + bv.y;
            *(float2*)(C + (size_t)m * Nout + n) = v0;
            *(float2*)(C + (size_t)(m + 8) * Nout + n) = v1;
        }
}

// ---------------- conversions ----------------------------------------------
__global__ void split_kernel(const float* __restrict__ in,
                             __nv_bfloat16* __restrict__ hi,
                             __nv_bfloat16* __restrict__ lo, int n)
{
    for (int i = blockIdx.x * blockDim.x + threadIdx.x; i < n; i += gridDim.x * blockDim.x) {
        float v = in[i];
        __nv_bfloat16 h = __float2bfloat16(v);
        hi[i] = h;
        lo[i] = __float2bfloat16(v - __bfloat162float(h));
    }
}
__global__ void stack_bias_kernel(const float* bk, const float* bq, const float* bv)
{
    int i = blockIdx.x * blockDim.x + threadIdx.x;
    if (i < Ee) {
        g_bias[i] = bk[i];
        g_bias[Ee + i] = bq[i];
        g_bias[2 * Ee + i] = bv[i];
    }
}

// store 4 fp32 as split hi/lo bf16 (8B each)
__device__ __forceinline__ void store_split4(float* o, size_t off) {
    __nv_bfloat16 h[4], l[4];
#pragma unroll
    for (int j = 0; j < 4; j++) {
        h[j] = __float2bfloat16(o[j]);
        l[j] = __float2bfloat16(o[j] - __bfloat162float(h[j]));
    }
    *(uint2*)(g_chi + off) = *(uint2*)h;
    *(uint2*)(g_clo + off) = *(uint2*)l;
}

// ---------------- head1: score (k-split) -----------------------------------
// grid (NBLK, Bb, KSPL): partial S over e in [ks*128, ks*128+128)
__global__ __launch_bounds__(256) void h1_score()
{
    const int blk = blockIdx.x, b = blockIdx.y, ks = blockIdx.z;
    const int tid = threadIdx.x;
    const int ty = tid >> 4, tx = tid & 15;
    const int lr = tid >> 2, lk = (tid & 3) * 4;
    const size_t rbase = (size_t)b * Tt + (size_t)blk * KBLK;
    const int e0beg = ks * (Ee / KSPL);

    __shared__ float Ks[16][68];
    __shared__ float Qs[16][68];

    float acc[4][4] = {};
    for (int e0 = e0beg; e0 < e0beg + Ee / KSPL; e0 += 16) {
        const float* rp = g_KQV + (rbase + lr) * NQKV;
        float4 vk = *(const float4*)(rp + e0 + lk);
        float4 vq = *(const float4*)(rp + Ee + e0 + lk);
        Ks[lk + 0][lr] = vk.x; Ks[lk + 1][lr] = vk.y;
        Ks[lk + 2][lr] = vk.z; Ks[lk + 3][lr] = vk.w;
        Qs[lk + 0][lr] = vq.x; Qs[lk + 1][lr] = vq.y;
        Qs[lk + 2][lr] = vq.z; Qs[lk + 3][lr] = vq.w;
        __syncthreads();
#pragma unroll
        for (int kk = 0; kk < 16; kk++) {
            float4 ra = *(const float4*)&Ks[kk][ty * 4];
            float4 rb = *(const float4*)&Qs[kk][tx * 4];
            float a_[4] = {ra.x, ra.y, ra.z, ra.w};
            float b_[4] = {rb.x, rb.y, rb.z, rb.w};
#pragma unroll
            for (int i = 0; i < 4; i++)
#pragma unroll
                for (int j = 0; j < 4; j++)
                    acc[i][j] += a_[i] * b_[j];
        }
        __syncthreads();
    }
    float* dst = g_S1part + (((size_t)ks * Bb + b) * NBLK + blk) * 4096;
#pragma unroll
    for (int i = 0; i < 4; i++) {
        int r = ty * 4 + i;
        *(float4*)(dst + r * 64 + tx * 4) = *(float4*)acc[i];
    }
}

// ---------------- head1: output (e-split) -----------------------------------
// grid (NBLK, Bb, ESPL): combine S partials, mask, S @ V for 128 e-cols
__global__ __launch_bounds__(256) void h1_out()
{
    const int blk = blockIdx.x, b = blockIdx.y, ec = blockIdx.z;
    const int tid = threadIdx.x;
    const int ty = tid >> 4, tx = tid & 15;
    const size_t rbase = (size_t)b * Tt + (size_t)blk * KBLK;

    __shared__ float Ssh[64][68];   // [c][r]
    __shared__ float Vs[64][68];

    const float* sp = g_S1part + (((size_t)b) * NBLK + blk) * 4096;
    const size_t kstride = (size_t)Bb * NBLK * 4096;
    for (int idx = tid; idx < 4096; idx += 256) {
        int r = idx >> 6, c = idx & 63;
        float s = sp[idx] + sp[idx + kstride] + sp[idx + 2 * kstride] + sp[idx + 3 * kstride];
        Ssh[c][r] = (c <= r) ? s : 0.0f;
    }
    __syncthreads();

    const int ebeg = ec * (Ee / ESPL);
    for (int e0 = ebeg; e0 < ebeg + Ee / ESPL; e0 += 64) {
#pragma unroll
        for (int l = 0; l < 4; l++) {
            int c = ty + l * 16;
            *(float4*)&Vs[c][tx * 4] =
                *(const float4*)(g_KQV + (rbase + c) * NQKV + 2 * Ee + e0 + tx * 4);
        }
        __syncthreads();
        float o[4][4] = {};
#pragma unroll 8
        for (int c = 0; c < 64; c++) {
            float4 rs = *(const float4*)&Ssh[c][ty * 4];
            float4 rv = *(const float4*)&Vs[c][tx * 4];
            float s_[4] = {rs.x, rs.y, rs.z, rs.w};
            float v_[4] = {rv.x, rv.y, rv.z, rv.w};
#pragma unroll
            for (int i = 0; i < 4; i++)
#pragma unroll
                for (int j = 0; j < 4; j++)
                    o[i][j] += s_[i] * v_[j];
        }
#pragma unroll
        for (int i = 0; i < 4; i++) {
            size_t row = rbase + ty * 4 + i;
            store_split4(o[i], row * COMB_W + e0 + tx * 4);
        }
        __syncthreads();
    }
}

// ---------------- head2: score (k-split) -----------------------------------
__global__ __launch_bounds__(256) void h2_score()
{
    const int rt = blockIdx.x, b = blockIdx.y, ks = blockIdx.z;
    const int tid = threadIdx.x;
    const int ty = tid >> 4, tx = tid & 15;
    const int lr = tid >> 2, lk = (tid & 3) * 4;
    const size_t rbase = (size_t)b * Tt + (size_t)rt * KBLK;
    const int e0beg = ks * (Ee / KSPL);

    __shared__ float Ks[16][68];
    __shared__ float Qs[16][36];

    float acc[4][2] = {};
    for (int e0 = e0beg; e0 < e0beg + Ee / KSPL; e0 += 16) {
        float4 vk = *(const float4*)(g_KQV + (rbase + lr) * NQKV + e0 + lk);
        Ks[lk + 0][lr] = vk.x; Ks[lk + 1][lr] = vk.y;
        Ks[lk + 2][lr] = vk.z; Ks[lk + 3][lr] = vk.w;
        if (tid < 128) {
            int qi = tid >> 2;
            float4 vq = *(const float4*)(g_KQV +
                ((size_t)b * Tt + (size_t)qi * KBLK) * NQKV + Ee + e0 + lk);
            Qs[lk + 0][qi] = vq.x; Qs[lk + 1][qi] = vq.y;
            Qs[lk + 2][qi] = vq.z; Qs[lk + 3][qi] = vq.w;
        }
        __syncthreads();
#pragma unroll
        for (int kk = 0; kk < 16; kk++) {
            float4 ra = *(const float4*)&Ks[kk][ty * 4];
            float a_[4] = {ra.x, ra.y, ra.z, ra.w};
            float q0 = Qs[kk][tx * 2 + 0];
            float q1 = Qs[kk][tx * 2 + 1];
#pragma unroll
            for (int i = 0; i < 4; i++) {
                acc[i][0] += a_[i] * q0;
                acc[i][1] += a_[i] * q1;
            }
        }
        __syncthreads();
    }
    float* dst = g_S2part + (((size_t)ks * Bb + b) * NBLK + rt) * 2048;
#pragma unroll
    for (int i = 0; i < 4; i++) {
        int r = ty * 4 + i;
        *(float2*)(dst + r * 32 + tx * 2) = *(float2*)acc[i];
    }
}

// ---------------- head2: output (e-split) -----------------------------------
__global__ __launch_bounds__(256) void h2_out()
{
    const int rt = blockIdx.x, b = blockIdx.y, ec = blockIdx.z;
    const int tid = threadIdx.x;
    const int ty = tid >> 4, tx = tid & 15;
    const size_t rbase = (size_t)b * Tt + (size_t)rt * KBLK;

    __shared__ float S2[32][68];    // [i][r]
    __shared__ float Vs[32][68];

    const float* sp = g_S2part + ((size_t)b * NBLK + rt) * 2048;
    const size_t kstride = (size_t)Bb * NBLK * 2048;
    for (int idx = tid; idx < 2048; idx += 256) {
        int r = idx >> 5, ii = idx & 31;
        float s = sp[idx] + sp[idx + kstride] + sp[idx + 2 * kstride] + sp[idx + 3 * kstride];
        S2[ii][r] = (ii <= rt) ? s : 0.0f;
    }
    __syncthreads();

    const int ebeg = ec * (Ee / ESPL);
    for (int e0 = ebeg; e0 < ebeg + Ee / ESPL; e0 += 64) {
#pragma unroll
        for (int l = 0; l < 2; l++) {
            int ii = (tid >> 4) + l * 16;
            *(float4*)&Vs[ii][(tid & 15) * 4] = *(const float4*)(g_KQV +
                ((size_t)b * Tt + (size_t)ii * KBLK) * NQKV + 2 * Ee + e0 + (tid & 15) * 4);
        }
        __syncthreads();
        float o[4][4] = {};
#pragma unroll 8
        for (int ii = 0; ii < 32; ii++) {
            float4 rs = *(const float4*)&S2[ii][ty * 4];
            float4 rv = *(const float4*)&Vs[ii][tx * 4];
            float s_[4] = {rs.x, rs.y, rs.z, rs.w};
            float v_[4] = {rv.x, rv.y, rv.z, rv.w};
#pragma unroll
            for (int i = 0; i < 4; i++)
#pragma unroll
                for (int j = 0; j < 4; j++)
                    o[i][j] += s_[i] * v_[j];
        }
#pragma unroll
        for (int i = 0; i < 4; i++) {
            size_t row = rbase + ty * 4 + i;
            store_split4(o[i], row * COMB_W + Ee + e0 + tx * 4);
        }
        __syncthreads();
    }
}

// ---------------------------------------------------------------------------
extern "C" void kernel_launch(void* const* d_in, const int* in_sizes, int n_in,
                              void* d_out, int out_size)
{
    const float* x  = (const float*)d_in[0];
    const float* Wk = (const float*)d_in[1];
    const float* bk = (const float*)d_in[2];
    const float* Wq = (const float*)d_in[3];
    const float* bq = (const float*)d_in[4];
    const float* Wv = (const float*)d_in[5];
    const float* bv = (const float*)d_in[6];
    const float* Wu = (const float*)d_in[7];
    const float* bu = (const float*)d_in[8];
    float* out = (float*)d_out;

    float *pKQV, *pBias;
    __nv_bfloat16 *pxh, *pxl, *pWh, *pWl, *pUh, *pUl, *pch, *pcl;
    cudaGetSymbolAddress((void**)&pKQV, g_KQV);
    cudaGetSymbolAddress((void**)&pBias, g_bias);
    cudaGetSymbolAddress((void**)&pxh, g_xhi);
    cudaGetSymbolAddress((void**)&pxl, g_xlo);
    cudaGetSymbolAddress((void**)&pWh, g_Whi);
    cudaGetSymbolAddress((void**)&pWl, g_Wlo);
    cudaGetSymbolAddress((void**)&pUh, g_Uhi);
    cudaGetSymbolAddress((void**)&pUl, g_Ulo);
    cudaGetSymbolAddress((void**)&pch, g_chi);
    cudaGetSymbolAddress((void**)&pcl, g_clo);

    cudaFuncSetAttribute(gemm_mma, cudaFuncAttributeMaxDynamicSharedMemorySize, GM_SMEM);

    // launches 1-5 (prereqs of QKV gemm)
    split_kernel<<<1024, 256>>>(x, pxh, pxl, MROWS * Ee);
    split_kernel<<<128, 256>>>(Wk, pWh, pWl, Ee * Ee);
    split_kernel<<<128, 256>>>(Wq, pWh + Ee * Ee, pWl + Ee * Ee, Ee * Ee);
    split_kernel<<<128, 256>>>(Wv, pWh + 2 * Ee * Ee, pWl + 2 * Ee * Ee, Ee * Ee);
    stack_bias_kernel<<<2, 256>>>(bk, bq, bv);

    // launch 6 — profiled by ncu (-s 5 -c 1)
    gemm_mma<<<dim3(NQKV / 128, MROWS / 128), 256, GM_SMEM>>>(
        pxh, pxl, pWh, pWl, pBias, pKQV, Ee, NQKV);

    // heads (k-split scores, then e-split outputs writing bf16 comb directly)
    h1_score<<<dim3(NBLK, Bb, KSPL), 256>>>();
    h2_score<<<dim3(NBLK, Bb, KSPL), 256>>>();
    h1_out<<<dim3(NBLK, Bb, ESPL), 256>>>();
    h2_out<<<dim3(NBLK, Bb, ESPL), 256>>>();

    // Wu split + final projection
    split_kernel<<<256, 256>>>(Wu, pUh, pUl, Ee * COMB_W);
    gemm_mma<<<dim3(Ee / 128, MROWS / 128), 256, GM_SMEM>>>(
        pch, pcl, pUh, pUl, bu, out, COMB_W, Ee);
}